// round 3
// baseline (speedup 1.0000x reference)
#include <cuda_runtime.h>

// Encoding layer: B=64, C=512, N=784 (28x28), K=32
// x layout: (B, C, N); out: (B, K, C) fp32

#define CDIM 512
#define KDIM 32
#define NPIX 784
#define BDIM 64
#define CHUNKS 9
#define TS 16
#define TILES_PER_B 49
#define XSTRIDE 516      // 512 + 4 pad: 8B-aligned rows, conflict-free LDS.64

typedef unsigned long long u64;

__device__ float g_wx[(size_t)BDIM * CHUNKS * KDIM * CDIM];
__device__ float g_wsum[BDIM * CHUNKS * KDIM];

__device__ __forceinline__ u64 pack2(float lo, float hi) {
    u64 r; asm("mov.b64 %0, {%1,%2};" : "=l"(r) : "f"(lo), "f"(hi)); return r;
}
__device__ __forceinline__ float2 unpack2(u64 v) {
    float2 r; asm("mov.b64 {%0,%1}, %2;" : "=f"(r.x), "=f"(r.y) : "l"(v)); return r;
}
#define FMA2(d, a, b, c) \
    asm("fma.rn.f32x2 %0, %1, %2, %3;" : "=l"(d) : "l"(a), "l"(b), "l"(c))

__global__ __launch_bounds__(256, 1)
void enc_main_kernel(const float* __restrict__ x,
                     const float* __restrict__ cw,
                     const float* __restrict__ scale) {
    const int b     = blockIdx.x / CHUNKS;
    const int chunk = blockIdx.x % CHUNKS;
    const int tile0 = (chunk * TILES_PER_B) / CHUNKS;
    const int tile1 = ((chunk + 1) * TILES_PER_B) / CHUNKS;
    const int t = threadIdx.x;
    const int w = t >> 5;     // warp 0..7 -> owns k in [4w, 4w+4)
    const int l = t & 31;     // lane -> owns c pairs (2l+64j, 2l+1+64j), j=0..7

    __shared__ float x_s[TS * XSTRIDE];
    __shared__ float xc_s[TS * KDIM];
    __shared__ float a_s[TS * KDIM];
    __shared__ float csq_s[KDIM];
    __shared__ float scl_s[KDIM];
    __shared__ float wsum_s[8][KDIM];

    // ---- codewords resident in registers, packed f32x2: cw2[kk][j] = cw[4w+kk][2l+64j .. +1]
    u64 cw2[4][8];
#pragma unroll
    for (int kk = 0; kk < 4; kk++) {
        const float2* cwp = (const float2*)(cw + (4 * w + kk) * CDIM);
#pragma unroll
        for (int j = 0; j < 8; j++) {
            float2 v = __ldg(&cwp[l + 32 * j]);
            cw2[kk][j] = pack2(v.x, v.y);
        }
    }

    // ---- c_sq per k (warp butterfly), scale into smem
#pragma unroll
    for (int kk = 0; kk < 4; kk++) {
        float s = 0.f;
#pragma unroll
        for (int j = 0; j < 8; j++) {
            float2 v = unpack2(cw2[kk][j]);
            s = fmaf(v.x, v.x, fmaf(v.y, v.y, s));
        }
#pragma unroll
        for (int o = 16; o; o >>= 1) s += __shfl_xor_sync(0xffffffffu, s, o);
        if (l == 0) csq_s[4 * w + kk] = s;
    }
    if (t < KDIM) scl_s[t] = __ldg(&scale[t]);

    u64 acc2[4][8];
#pragma unroll
    for (int kk = 0; kk < 4; kk++)
#pragma unroll
        for (int j = 0; j < 8; j++) acc2[kk][j] = 0ull;
    float wsum_acc = 0.f;

    const float* xb = x + (size_t)b * CDIM * NPIX;
    const int nl = t & 15;   // row loaded by this thread
    const int cb = t >> 4;   // c base for staging loads

    for (int tile = tile0; tile < tile1; tile++) {
        const int n0 = tile * TS;
        __syncthreads();                       // x_s / a_s reuse fence

        // ---- stage x tile (coalesced: warp covers 2 c-rows x 16 n = 128B/LDG)
#pragma unroll
        for (int i = 0; i < 32; i++) {
            int c = cb + 16 * i;
            x_s[nl * XSTRIDE + c] = __ldg(&xb[c * NPIX + n0 + nl]);
        }
        __syncthreads();

        // ---- phase 1: xc[n][k] dots, packed f32x2, rows in pairs for shfl ILP
        for (int np = 0; np < TS; np += 2) {
            u64 s2[2][4];
#pragma unroll
            for (int r = 0; r < 2; r++) {
                const u64* xrow = (const u64*)(x_s + (np + r) * XSTRIDE);
                u64 a0 = 0ull, a1 = 0ull, a2 = 0ull, a3 = 0ull;
#pragma unroll
                for (int j = 0; j < 8; j++) {
                    u64 xv = xrow[l + 32 * j];
                    FMA2(a0, xv, cw2[0][j], a0);
                    FMA2(a1, xv, cw2[1][j], a1);
                    FMA2(a2, xv, cw2[2][j], a2);
                    FMA2(a3, xv, cw2[3][j], a3);
                }
                s2[r][0] = a0; s2[r][1] = a1; s2[r][2] = a2; s2[r][3] = a3;
            }
            float v[2][4];
#pragma unroll
            for (int r = 0; r < 2; r++)
#pragma unroll
                for (int kk = 0; kk < 4; kk++) {
                    float2 p = unpack2(s2[r][kk]);
                    v[r][kk] = p.x + p.y;
                }
#pragma unroll
            for (int o = 16; o; o >>= 1)
#pragma unroll
                for (int r = 0; r < 2; r++)
#pragma unroll
                    for (int kk = 0; kk < 4; kk++)
                        v[r][kk] += __shfl_xor_sync(0xffffffffu, v[r][kk], o);
            if (l == 0) {
                *(float4*)&xc_s[(np + 0) * KDIM + 4 * w] =
                    make_float4(v[0][0], v[0][1], v[0][2], v[0][3]);
                *(float4*)&xc_s[(np + 1) * KDIM + 4 * w] =
                    make_float4(v[1][0], v[1][1], v[1][2], v[1][3]);
            }
        }
        __syncthreads();

        // ---- softmax: warp w handles rows w and w+8; lane = k; xsq computed inline
#pragma unroll
        for (int r = 0; r < 2; r++) {
            int n = w + 8 * r;
            float xs = 0.f;
#pragma unroll
            for (int j = 0; j < 16; j++) {
                float xv = x_s[n * XSTRIDE + l + 32 * j];
                xs = fmaf(xv, xv, xs);
            }
#pragma unroll
            for (int o = 16; o; o >>= 1) xs += __shfl_xor_sync(0xffffffffu, xs, o);

            float xc = xc_s[n * KDIM + l];
            float d = scl_s[l] * (xs - 2.f * xc + csq_s[l]);
            float m = d;
#pragma unroll
            for (int o = 16; o; o >>= 1) m = fmaxf(m, __shfl_xor_sync(0xffffffffu, m, o));
            float e = __expf(d - m);
            float ssum = e;
#pragma unroll
            for (int o = 16; o; o >>= 1) ssum += __shfl_xor_sync(0xffffffffu, ssum, o);
            float a = __fdividef(e, ssum);
            a_s[n * KDIM + l] = a;
            wsum_acc += a;
        }
        __syncthreads();

        // ---- phase 2: wx[k][c] += A[n][k] * x[n][c], packed f32x2
        for (int n = 0; n < TS; n++) {
            float4 av = *(const float4*)&a_s[n * KDIM + 4 * w];  // broadcast
            u64 p0 = pack2(av.x, av.x);
            u64 p1 = pack2(av.y, av.y);
            u64 p2 = pack2(av.z, av.z);
            u64 p3 = pack2(av.w, av.w);
            const u64* xrow = (const u64*)(x_s + n * XSTRIDE);
#pragma unroll
            for (int j = 0; j < 8; j++) {
                u64 xv = xrow[l + 32 * j];
                FMA2(acc2[0][j], p0, xv, acc2[0][j]);
                FMA2(acc2[1][j], p1, xv, acc2[1][j]);
                FMA2(acc2[2][j], p2, xv, acc2[2][j]);
                FMA2(acc2[3][j], p3, xv, acc2[3][j]);
            }
        }
    }

    // ---- write per-chunk partials (float2, coalesced)
    float* wxp = g_wx + (size_t)(b * CHUNKS + chunk) * KDIM * CDIM;
#pragma unroll
    for (int kk = 0; kk < 4; kk++)
#pragma unroll
        for (int j = 0; j < 8; j++) {
            float2 p = unpack2(acc2[kk][j]);
            *(float2*)&wxp[(4 * w + kk) * CDIM + 2 * l + 64 * j] = p;
        }

    wsum_s[w][l] = wsum_acc;
    __syncthreads();
    if (t < KDIM) {
        float s = 0.f;
#pragma unroll
        for (int ww = 0; ww < 8; ww++) s += wsum_s[ww][t];
        g_wsum[(b * CHUNKS + chunk) * KDIM + t] = s;
    }
}

__global__ void enc_epilogue_kernel(const float* __restrict__ cw,
                                    float* __restrict__ out) {
    int idx = blockIdx.x * blockDim.x + threadIdx.x;  // over B*K*C/4 float4s
    int c4 = idx & (CDIM / 4 - 1);
    int k  = (idx >> 7) & (KDIM - 1);
    int b  = idx >> 12;

    float4 s = make_float4(0.f, 0.f, 0.f, 0.f);
    float ws = 0.f;
#pragma unroll
    for (int ch = 0; ch < CHUNKS; ch++) {
        const float4* p = (const float4*)(g_wx +
            (size_t)(b * CHUNKS + ch) * KDIM * CDIM + k * CDIM) + c4;
        float4 v = *p;
        s.x += v.x; s.y += v.y; s.z += v.z; s.w += v.w;
        ws  += g_wsum[(b * CHUNKS + ch) * KDIM + k];
    }
    float4 cv = *((const float4*)(cw + k * CDIM) + c4);
    float4 o;
    o.x = s.x - ws * cv.x;
    o.y = s.y - ws * cv.y;
    o.z = s.z - ws * cv.z;
    o.w = s.w - ws * cv.w;
    *((float4*)out + idx) = o;
}

extern "C" void kernel_launch(void* const* d_in, const int* in_sizes, int n_in,
                              void* d_out, int out_size) {
    const float* x     = (const float*)d_in[0];
    const float* cw    = (const float*)d_in[1];
    const float* scale = (const float*)d_in[2];
    float* out = (float*)d_out;

    enc_main_kernel<<<BDIM * CHUNKS, 256>>>(x, cw, scale);
    enc_epilogue_kernel<<<(BDIM * KDIM * CDIM / 4) / 256, 256>>>(cw, out);
}

// round 5
// speedup vs baseline: 1.2741x; 1.2741x over previous
#include <cuda_runtime.h>
#include <cstdint>

// Encoding: B=64, C=512, N=784, K=32. x:(B,C,N) f32; out:(B,K,C) f32.
// K1: logits via mma.sync tf32 + softmax -> A (tf32) to gmem + wsum partials.
// K2: out = A^T x (tf32 hi/lo split, fp32-accurate) - wsum*cw, fused epilogue.

#define CDIM 512
#define KD 32
#define NPIX 784
#define BDIM 64
#define CH1 9
#define TS 16
#define TILES1 49
#define CB2 8          // K2: c-blocks of 64

__device__ float g_A[(size_t)BDIM * NPIX * KD];     // 6.4 MB
__device__ float g_wsum[BDIM * CH1 * KD];

__device__ __forceinline__ float rtf32(float v) {
    asm("cvt.rna.tf32.f32 %0, %1;" : "=f"(v) : "f"(v));
    return v;
}
__device__ __forceinline__ void mma8(float* d, uint32_t a0, uint32_t a1,
                                     uint32_t a2, uint32_t a3,
                                     uint32_t b0, uint32_t b1) {
    asm volatile(
        "mma.sync.aligned.m16n8k8.row.col.f32.tf32.tf32.f32 "
        "{%0,%1,%2,%3}, {%4,%5,%6,%7}, {%8,%9}, {%0,%1,%2,%3};"
        : "+f"(d[0]), "+f"(d[1]), "+f"(d[2]), "+f"(d[3])
        : "r"(a0), "r"(a1), "r"(a2), "r"(a3), "r"(b0), "r"(b1));
}
#define BITS(f) __float_as_uint(f)

// =========================== K1: logits + softmax ===========================
__global__ __launch_bounds__(256) void enc_k1(const float* __restrict__ x,
                                              const float* __restrict__ cw,
                                              const float* __restrict__ scale) {
    const int b = blockIdx.x / CH1, ch = blockIdx.x % CH1;
    const int tile0 = ch * TILES1 / CH1, tile1 = (ch + 1) * TILES1 / CH1;
    const int t = threadIdx.x, w = t >> 5, l = t & 31;
    const int kt = w & 3, h = w >> 2;         // warp = (k-tile, c-half)

    __shared__ float x_s[TS * 516];
    __shared__ float xc_s[TS * 34];
    __shared__ float red_s[4 * 32 * 4];
    __shared__ float csq_s[KD], scl_s[KD];
    __shared__ float wsum_s[8][KD];

    if (t < KD) scl_s[t] = __ldg(&scale[t]);
    // csq from tf32-rounded cw: warp w -> k = 4w..4w+3, lane covers 16 c
#pragma unroll
    for (int kk = 0; kk < 4; kk++) {
        int k = 4 * w + kk;
        float s = 0.f;
#pragma unroll
        for (int q = 0; q < 4; q++) {
            float4 v = __ldg((const float4*)&cw[k * CDIM + l * 16 + 4 * q]);
            float e0 = rtf32(v.x), e1 = rtf32(v.y), e2 = rtf32(v.z), e3 = rtf32(v.w);
            s += e0 * e0 + e1 * e1 + e2 * e2 + e3 * e3;
        }
#pragma unroll
        for (int o = 16; o; o >>= 1) s += __shfl_xor_sync(~0u, s, o);
        if (l == 0) csq_s[k] = s;
    }

    // persistent codeword B-fragments (tf32): warp covers k=8kt..+7, c-half h
    uint32_t cwf0[32], cwf1[32];
    const int crow = kt * 8 + (l >> 2), cp = l & 3;
#pragma unroll
    for (int s = 0; s < 32; s++) {
        int c = h * 256 + 8 * s + cp;
        cwf0[s] = BITS(rtf32(__ldg(&cw[crow * CDIM + c])));
        cwf1[s] = BITS(rtf32(__ldg(&cw[crow * CDIM + c + 4])));
    }

    float wsum_acc = 0.f;
    const float* xb = x + (size_t)b * CDIM * NPIX;
    const int nl = t & 15, cb16 = t >> 4;

    for (int tile = tile0; tile < tile1; tile++) {
        const int n0 = tile * TS;
        __syncthreads();
        // stage x tile (tf32-rounded), coalesced as round-2
#pragma unroll
        for (int i = 0; i < 32; i++) {
            int c = cb16 + 16 * i;
            x_s[nl * 516 + c] = rtf32(__ldg(&xb[c * NPIX + n0 + nl]));
        }
        __syncthreads();

        // phase 1: xc = x . cw^T, 32 k-steps, 2 accumulation chains
        float dA[4] = {0.f, 0.f, 0.f, 0.f}, dB[4] = {0.f, 0.f, 0.f, 0.f};
        const int r0 = (l >> 2) * 516, r1 = ((l >> 2) + 8) * 516;
#pragma unroll
        for (int s = 0; s < 32; s++) {
            int c = h * 256 + 8 * s + cp;
            uint32_t a0 = BITS(x_s[r0 + c]);
            uint32_t a1 = BITS(x_s[r1 + c]);
            uint32_t a2 = BITS(x_s[r0 + c + 4]);
            uint32_t a3 = BITS(x_s[r1 + c + 4]);
            mma8((s & 1) ? dB : dA, a0, a1, a2, a3, cwf0[s], cwf1[s]);
        }
        float d4[4];
#pragma unroll
        for (int i = 0; i < 4; i++) d4[i] = dA[i] + dB[i];
        if (h == 1)
            *(float4*)&red_s[(kt * 32 + l) * 4] = make_float4(d4[0], d4[1], d4[2], d4[3]);
        __syncthreads();
        if (h == 0) {
            float4 rr = *(const float4*)&red_s[(kt * 32 + l) * 4];
            d4[0] += rr.x; d4[1] += rr.y; d4[2] += rr.z; d4[3] += rr.w;
            int rrow = l >> 2, cc = kt * 8 + 2 * (l & 3);
            *(float2*)&xc_s[rrow * 34 + cc] = make_float2(d4[0], d4[1]);
            *(float2*)&xc_s[(rrow + 8) * 34 + cc] = make_float2(d4[2], d4[3]);
        }
        __syncthreads();

        // softmax: warp w rows {w, w+8}, lane = k
#pragma unroll
        for (int r = 0; r < 2; r++) {
            int n = w + 8 * r;
            float xs = 0.f;
#pragma unroll
            for (int j = 0; j < 16; j++) {
                float xv = x_s[n * 516 + l + 32 * j];
                xs = fmaf(xv, xv, xs);
            }
#pragma unroll
            for (int o = 16; o; o >>= 1) xs += __shfl_xor_sync(~0u, xs, o);
            float xc = xc_s[n * 34 + l];
            float dd = scl_s[l] * (xs - 2.f * xc + csq_s[l]);
            float m = dd;
#pragma unroll
            for (int o = 16; o; o >>= 1) m = fmaxf(m, __shfl_xor_sync(~0u, m, o));
            float e = __expf(dd - m);
            float ss = e;
#pragma unroll
            for (int o = 16; o; o >>= 1) ss += __shfl_xor_sync(~0u, ss, o);
            float a = rtf32(__fdividef(e, ss));   // store A as exact tf32
            wsum_acc += a;
            g_A[((size_t)b * NPIX + n0 + n) * KD + l] = a;
        }
    }

    wsum_s[w][l] = wsum_acc;
    __syncthreads();
    if (t < KD) {
        float s = 0.f;
#pragma unroll
        for (int ww = 0; ww < 8; ww++) s += wsum_s[ww][t];
        g_wsum[(b * CH1 + ch) * KD + t] = s;
    }
}

// ================= K2: out = A^T x (hi/lo tf32) - wsum*cw =================
__global__ __launch_bounds__(256) void enc_k2(const float* __restrict__ x,
                                              const float* __restrict__ cw,
                                              float* __restrict__ out) {
    const int b = blockIdx.x >> 3, cb = blockIdx.x & 7;
    const int t = threadIdx.x, w = t >> 5, l = t & 31;
    const int mt = w & 1, cq = w >> 1;   // warp = (k-half of 16, 16-c quarter)

    __shared__ float A_s[TS * 40];
    __shared__ float xhi[64 * 20], xlo[64 * 20];
    __shared__ float wsum_s[KD];

    if (t < KD) {
        float s = 0.f;
#pragma unroll
        for (int ch = 0; ch < CH1; ch++) s += g_wsum[(b * CH1 + ch) * KD + t];
        wsum_s[t] = s;
    }
    float acc[2][4];
#pragma unroll
    for (int i = 0; i < 2; i++)
#pragma unroll
        for (int j = 0; j < 4; j++) acc[i][j] = 0.f;

    const float* xb = x + (size_t)b * CDIM * NPIX + (size_t)(cb * 64) * NPIX;
    const float* Ab = g_A + (size_t)b * NPIX * KD;
    const int sr = t >> 2, sq = t & 3;   // x staging: row (64), quarter
    const int an = t >> 4, ak = t & 15;  // A staging

    for (int tl = 0; tl < TILES1; tl++) {
        const int n0 = tl * TS;
        __syncthreads();
        {   // A tile [16n x 32k] (already tf32)
            float2 av = *(const float2*)&Ab[(size_t)(n0 + an) * KD + 2 * ak];
            A_s[an * 40 + 2 * ak] = av.x;
            A_s[an * 40 + 2 * ak + 1] = av.y;
            // x block [64c x 16n], hi/lo tf32 split
            float4 v = __ldg((const float4*)&xb[sr * NPIX + n0 + 4 * sq]);
            float h0 = rtf32(v.x), h1 = rtf32(v.y), h2 = rtf32(v.z), h3 = rtf32(v.w);
            int ba = sr * 20 + 4 * sq;
            xhi[ba + 0] = h0; xhi[ba + 1] = h1; xhi[ba + 2] = h2; xhi[ba + 3] = h3;
            xlo[ba + 0] = rtf32(v.x - h0); xlo[ba + 1] = rtf32(v.y - h1);
            xlo[ba + 2] = rtf32(v.z - h2); xlo[ba + 3] = rtf32(v.w - h3);
        }
        __syncthreads();
#pragma unroll
        for (int ks = 0; ks < 2; ks++) {
            int prow = 8 * ks + (l & 3);
            uint32_t a0 = BITS(A_s[prow * 40 + mt * 16 + (l >> 2)]);
            uint32_t a1 = BITS(A_s[prow * 40 + mt * 16 + (l >> 2) + 8]);
            uint32_t a2 = BITS(A_s[(prow + 4) * 40 + mt * 16 + (l >> 2)]);
            uint32_t a3 = BITS(A_s[(prow + 4) * 40 + mt * 16 + (l >> 2) + 8]);
#pragma unroll
            for (int nt = 0; nt < 2; nt++) {
                int crow = cq * 16 + nt * 8 + (l >> 2);
                int pp = 8 * ks + (l & 3);
                uint32_t b0 = BITS(xhi[crow * 20 + pp]);
                uint32_t b1 = BITS(xhi[crow * 20 + pp + 4]);
                mma8(acc[nt], a0, a1, a2, a3, b0, b1);
                b0 = BITS(xlo[crow * 20 + pp]);
                b1 = BITS(xlo[crow * 20 + pp + 4]);
                mma8(acc[nt], a0, a1, a2, a3, b0, b1);
            }
        }
    }

    // fused epilogue: out = acc - wsum*cw
#pragma unroll
    for (int nt = 0; nt < 2; nt++) {
        int cg = cb * 64 + cq * 16 + nt * 8 + 2 * (l & 3);
        int k0 = mt * 16 + (l >> 2);
#pragma unroll
        for (int half = 0; half < 2; half++) {
            int k = k0 + 8 * half;
            float2 cv = __ldg((const float2*)&cw[k * CDIM + cg]);
            float ws = wsum_s[k];
            float2 o;
            o.x = acc[nt][2 * half]     - ws * cv.x;
            o.y = acc[nt][2 * half + 1] - ws * cv.y;
            *(float2*)&out[((size_t)b * KD + k) * CDIM + cg] = o;
        }
    }
}

extern "C" void kernel_launch(void* const* d_in, const int* in_sizes, int n_in,
                              void* d_out, int out_size) {
    const float* x     = (const float*)d_in[0];
    const float* cw    = (const float*)d_in[1];
    const float* scale = (const float*)d_in[2];
    enc_k1<<<BDIM * CH1, 256>>>(x, cw, scale);
    enc_k2<<<BDIM * CB2, 256>>>(x, cw, (float*)d_out);
}